// round 12
// baseline (speedup 1.0000x reference)
#include <cuda_runtime.h>
#include <cuda_fp16.h>
#include <cstdint>

#define B_N 2048
#define H_N 4096
#define E_N 8
#define L_N 512

// ---------------- scratch ----------------
__device__ int   g_counts[E_N];
__device__ int   g_rows[E_N][B_N];
__device__ float g_pen[25];
__device__ int   g_ntiles;
__device__ int   g_tile_ctr;
__device__ uint32_t g_tiles[512];

__device__ __align__(256) __half g_hid_h[B_N * H_N];
__device__ __align__(256) __half g_W_h[E_N * L_N * H_N];

__global__ void init_kernel() {
    int t = threadIdx.x;
    if (t < E_N) g_counts[t] = 0;
    if (t < 25)  g_pen[t]    = 0.0f;
    if (t == 0)  g_tile_ctr  = 0;
}

// ---------------- expert selection ----------------
__global__ void select_kernel(const float* __restrict__ envs,
                              const int* __restrict__ idx32,
                              const float* __restrict__ gumbel) {
    int b = blockIdx.x * blockDim.x + threadIdx.x;
    if (b >= B_N) return;
    int stride = (idx32[1] == 0) ? 2 : 1;   // int64-on-disk detection (idx = arange)
    int r = idx32[(size_t)b * stride];
    if (r < 0) r = 0;
    if (r >= B_N) r = B_N - 1;
    const float* ev = envs   + (size_t)r * E_N;
    const float* gv = gumbel + (size_t)b * E_N;
    float best = ev[0] + gv[0];
    int be = 0;
#pragma unroll
    for (int e = 1; e < E_N; e++) {
        float v = ev[e] + gv[e];
        if (v > best) { best = v; be = e; }
    }
    int pos = atomicAdd(&g_counts[be], 1);
    g_rows[be][pos] = b;
}

// ---------------- balanced tile list ----------------
// tile = (expert, 128-row m-chunk, 64-col l-block); enc = e<<12 | m<<4 | l
__global__ void build_tiles_kernel() {
    if (threadIdx.x == 0) {
        int n = 0;
        for (int e = 0; e < E_N; e++) {
            int mc = (g_counts[e] + 127) >> 7;
            for (int m = 0; m < mc; m++)
                for (int l = 0; l < 8; l++)
                    g_tiles[n++] = (e << 12) | (m << 4) | l;
        }
        g_ntiles = n;
    }
}

// ------- penalty + W -> fp16 + hidden -> fp16, fused single pass -------
// grid*block must divide LH4: 1024 * 128 = 131072; LH4 = 524288 -> 4 iters.
#define PEN_GRID 1024
#define PEN_BLK  128

__global__ void __launch_bounds__(PEN_BLK, 4)
penalty_kernel(const float* __restrict__ W, const float* __restrict__ hidden) {
    const int LH4 = (L_N * H_N) / 4;
    const float4* Wv = (const float4*)W;
    uint2* wh = (uint2*)g_W_h;
    const int stride = PEN_GRID * PEN_BLK;
    const int iters = LH4 / stride;   // 4

    float q[8], c[8], l1[8], ss = 0.0f;
#pragma unroll
    for (int e = 0; e < 8; e++) { q[e] = 0.f; c[e] = 0.f; l1[e] = 0.f; }

    int i = blockIdx.x * PEN_BLK + threadIdx.x;

    float4 buf[8];
#pragma unroll
    for (int e = 0; e < 8; e++) buf[e] = Wv[(size_t)e * LH4 + i];

    for (int it = 0; it < iters; it++) {
        float4 nxt[8];
        int i2 = i + stride;
        if (it + 1 < iters) {
#pragma unroll
            for (int e = 0; e < 8; e++) nxt[e] = Wv[(size_t)e * LH4 + i2];
        }
        // convert + store fp16
#pragma unroll
        for (int e = 0; e < 8; e++) {
            float4 v = buf[e];
            __half2 h01 = __floats2half2_rn(v.x, v.y);
            __half2 h23 = __floats2half2_rn(v.z, v.w);
            uint2 p;
            p.x = *reinterpret_cast<uint32_t*>(&h01);
            p.y = *reinterpret_cast<uint32_t*>(&h23);
            wh[(size_t)e * LH4 + i] = p;
        }
        // stats
#pragma unroll
        for (int comp = 0; comp < 4; comp++) {
            float we[8];
#pragma unroll
            for (int e = 0; e < 8; e++) {
                float4 t = buf[e];
                we[e] = (comp == 0) ? t.x : (comp == 1) ? t.y : (comp == 2) ? t.z : t.w;
            }
            float s = 0.f;
#pragma unroll
            for (int e = 0; e < 8; e++) s += we[e];
            ss = fmaf(s, s, ss);
#pragma unroll
            for (int e = 0; e < 8; e++) {
                q[e]  = fmaf(we[e], we[e], q[e]);
                c[e]  = fmaf(we[e], s,     c[e]);
                l1[e] += fabsf(we[e]);
            }
        }
        if (it + 1 < iters) {
#pragma unroll
            for (int e = 0; e < 8; e++) buf[e] = nxt[e];
            i = i2;
        }
    }

    // fused hidden -> fp16 (16 strided iterations)
    {
        const int hn4 = B_N * H_N / 4;
        const float4* hv = (const float4*)hidden;
        uint2* hh = (uint2*)g_hid_h;
        for (int j = blockIdx.x * PEN_BLK + threadIdx.x; j < hn4; j += stride) {
            float4 v = hv[j];
            __half2 h01 = __floats2half2_rn(v.x, v.y);
            __half2 h23 = __floats2half2_rn(v.z, v.w);
            uint2 p;
            p.x = *reinterpret_cast<uint32_t*>(&h01);
            p.y = *reinterpret_cast<uint32_t*>(&h23);
            hh[j] = p;
        }
    }

    __shared__ float red[25][136];
    int tid = threadIdx.x;
#pragma unroll
    for (int e = 0; e < 8; e++) {
        red[e][tid]      = q[e];
        red[8 + e][tid]  = c[e];
        red[16 + e][tid] = l1[e];
    }
    red[24][tid] = ss;
    __syncthreads();
    if (tid < 25) {
        float s = 0.f;
#pragma unroll 8
        for (int j = 0; j < PEN_BLK; j++) s += red[tid][j];
        atomicAdd(&g_pen[tid], s);
    }
}

__global__ void finalize_kernel(float* __restrict__ pen_out) {
    if (threadIdx.x == 0) {
        float acc = 0.f;
        float ss = g_pen[24];
#pragma unroll
        for (int e = 0; e < 8; e++) {
            float diff = g_pen[e] - 0.25f * g_pen[8 + e] + ss * (1.0f / 64.0f);
            float l1 = g_pen[16 + e];
            acc += diff / (l1 * l1);
        }
        pen_out[0] = acc * 0.125f;
    }
}

// ====== persistent fp16 tensor-core grouped GEMM (1 CTA/SM) ======
// CTA tile 128(M) x 64(N) x 64(K); 128 threads = 4 warps (2M x 2N), warp 64x32.
// MAC/smem ratio 10.7 (vs 8.0 at 32x32) -> crossbar no longer serializes tensor.
// Stage (bytes): A 16K | B 8K = 24KB; 4 stages = 96KB.
// Swizzle: row stride 64 halves (128B), 16B chunk phys = chunk ^ (row & 7).

#define TMB 128
#define TNB 64
#define TK 64
#define NSTAGE 4
#define STG_B 24576
#define NIT (H_N / TK)          // 64
#define SMEM_DYN (NSTAGE * STG_B + 1024)
#define GRID_GEMM 148

static __device__ __forceinline__ uint32_t s2u(const void* p) {
    return (uint32_t)__cvta_generic_to_shared(p);
}
static __device__ __forceinline__ void cp16(uint32_t s, const __half* g, bool pred) {
    int sz = pred ? 16 : 0;
    asm volatile("cp.async.cg.shared.global [%0], [%1], 16, %2;"
                 :: "r"(s), "l"(g), "r"(sz));
}

#define LDSM4(r0, r1, r2, r3, a) \
    asm volatile("ldmatrix.sync.aligned.m8n8.x4.shared.b16 {%0,%1,%2,%3}, [%4];" \
                 : "=r"(r0), "=r"(r1), "=r"(r2), "=r"(r3) : "r"(a))

#define MMAF16(d, A, b0, b1) \
    asm volatile("mma.sync.aligned.m16n8k16.row.col.f32.f16.f16.f32 " \
                 "{%0,%1,%2,%3}, {%4,%5,%6,%7}, {%8,%9}, {%0,%1,%2,%3};" \
                 : "+f"((d)[0]), "+f"((d)[1]), "+f"((d)[2]), "+f"((d)[3]) \
                 : "r"((A)[0]), "r"((A)[1]), "r"((A)[2]), "r"((A)[3]), \
                   "r"(b0), "r"(b1))

extern __shared__ char dyn_raw[];

__global__ void __launch_bounds__(128, 1)
gemm_kernel(float* __restrict__ out) {
    __shared__ int rowids[TMB];
    __shared__ int s_tile;

    int tid = threadIdx.x;
    int wid = tid >> 5, lane = tid & 31;

    uint32_t sbase = (s2u(dyn_raw) + 1023) & ~1023u;
    uint32_t stb[NSTAGE];
#pragma unroll
    for (int s = 0; s < NSTAGE; s++) stb[s] = sbase + s * STG_B;

    // loader geometry: 16B chunks; A 1024 slots (8/thr), B 512 slots (4/thr)
    int lrow = tid >> 3;              // 0..15
    int lcc  = tid & 7;
    int lphys = lcc ^ (lrow & 7);     // row&7 invariant (rows step by 16)
    int sOffA[8], sOffB[4];
#pragma unroll
    for (int i = 0; i < 8; i++) sOffA[i] = ((lrow + i * 16) * 64 + lphys * 8) * 2;
#pragma unroll
    for (int i = 0; i < 4; i++) sOffB[i] = ((lrow + i * 16) * 64 + lphys * 8) * 2;

    // warp geometry: warp tile 64(M) x 32(N); warps 2M x 2N
    int wm = (wid & 1) * 64;
    int wn = (wid >> 1) * 32;
    int a_r = lane & 15, a_h = lane >> 4;
    int b_g = lane >> 3, b_sub = b_g >> 1, b_h = b_g & 1, b_r = lane & 7;

    int arow[4], axr[4];
#pragma unroll
    for (int mt = 0; mt < 4; mt++) {
        int r = wm + mt * 16 + a_r;
        arow[mt] = r * 64; axr[mt] = r & 7;
    }
    int brow[2], bxr[2];
#pragma unroll
    for (int p = 0; p < 2; p++) {
        int r = wn + p * 16 + b_sub * 8 + b_r;
        brow[p] = r * 64; bxr[p] = r & 7;
    }
    int gid = lane >> 2, tig = lane & 3;

    for (;;) {
        __syncthreads();   // previous tile fully done
        if (tid == 0) s_tile = atomicAdd(&g_tile_ctr, 1);
        __syncthreads();
        int t = s_tile;
        if (t >= g_ntiles) break;

        uint32_t enc = g_tiles[t];
        int e = enc >> 12;
        int mch = (enc >> 4) & 255;
        int l_base = (enc & 15) * TNB;
        int cnt = g_counts[e];

        if (tid < TMB) {
            int i = mch * TMB + tid;
            rowids[tid] = (i < cnt) ? g_rows[e][i] : -1;
        }
        __syncthreads();

        const __half* gA[8];
        const __half* gB[4];
        bool apred[8];
#pragma unroll
        for (int i = 0; i < 8; i++) {
            int row = lrow + i * 16;
            int g = rowids[row];
            apred[i] = (g >= 0);
            gA[i] = g_hid_h + (size_t)(apred[i] ? g : 0) * H_N + lcc * 8;
        }
#pragma unroll
        for (int i = 0; i < 4; i++) {
            int row = lrow + i * 16;
            gB[i] = g_W_h + ((size_t)e * L_N + l_base + row) * H_N + lcc * 8;
        }

        float acc[4][4][4];
#pragma unroll
        for (int mt = 0; mt < 4; mt++)
#pragma unroll
            for (int nt = 0; nt < 4; nt++)
#pragma unroll
                for (int j = 0; j < 4; j++) acc[mt][nt][j] = 0.f;

        // preload stages 0..2
#pragma unroll
        for (int p = 0; p < NSTAGE - 1; p++) {
            uint32_t b = stb[p];
            int koff = p * TK;
#pragma unroll
            for (int i = 0; i < 8; i++) cp16(b + sOffA[i], gA[i] + koff, apred[i]);
#pragma unroll
            for (int i = 0; i < 4; i++) cp16(b + 16384 + sOffB[i], gB[i] + koff, true);
            asm volatile("cp.async.commit_group;");
        }

        int cur = 0, nxt = NSTAGE - 1;
        for (int it = 0; it < NIT; it++) {
            asm volatile("cp.async.wait_group 2;");
            __syncthreads();

            int nc = it + NSTAGE - 1;
            if (nc < NIT) {
                uint32_t b = stb[nxt];
                int koff = nc * TK;
#pragma unroll
                for (int i = 0; i < 8; i++) cp16(b + sOffA[i], gA[i] + koff, apred[i]);
#pragma unroll
                for (int i = 0; i < 4; i++) cp16(b + 16384 + sOffB[i], gB[i] + koff, true);
            }
            asm volatile("cp.async.commit_group;");

            uint32_t AS = stb[cur];
            uint32_t BS = AS + 16384;

#pragma unroll
            for (int s4 = 0; s4 < 4; s4++) {
                uint32_t af[4][4], bf[4][2];
#pragma unroll
                for (int mt = 0; mt < 4; mt++) {
                    int ch = (2 * s4 + a_h) ^ axr[mt];
                    LDSM4(af[mt][0], af[mt][1], af[mt][2], af[mt][3],
                          AS + (arow[mt] + ch * 8) * 2);
                }
#pragma unroll
                for (int p = 0; p < 2; p++) {
                    int ch = (2 * s4 + b_h) ^ bxr[p];
                    uint32_t r0, r1, r2, r3;
                    LDSM4(r0, r1, r2, r3, BS + (brow[p] + ch * 8) * 2);
                    bf[2 * p][0] = r0; bf[2 * p][1] = r1;
                    bf[2 * p + 1][0] = r2; bf[2 * p + 1][1] = r3;
                }
                // 16 independent MMAs (each acc touched once per s4)
#pragma unroll
                for (int mt = 0; mt < 4; mt++)
#pragma unroll
                    for (int nt = 0; nt < 4; nt++)
                        MMAF16(acc[mt][nt], af[mt], bf[nt][0], bf[nt][1]);
            }
            cur = (cur + 1 == NSTAGE) ? 0 : cur + 1;
            nxt = (nxt + 1 == NSTAGE) ? 0 : nxt + 1;
        }

        // ---- epilogue ----
#pragma unroll
        for (int mt = 0; mt < 4; mt++) {
            int r0 = wm + mt * 16 + gid;
            int r1 = r0 + 8;
            int g0 = rowids[r0];
            int g1 = rowids[r1];
#pragma unroll
            for (int nt = 0; nt < 4; nt++) {
                int col = l_base + wn + nt * 8 + tig * 2;
                if (g0 >= 0)
                    *(float2*)(out + (size_t)g0 * L_N + col) =
                        make_float2(acc[mt][nt][0], acc[mt][nt][1]);
                if (g1 >= 0)
                    *(float2*)(out + (size_t)g1 * L_N + col) =
                        make_float2(acc[mt][nt][2], acc[mt][nt][3]);
            }
        }
    }
}

// ---------------- launch ----------------
extern "C" void kernel_launch(void* const* d_in, const int* in_sizes, int n_in,
                              void* d_out, int out_size) {
    const float* hidden = (const float*)d_in[0];
    const float* envs   = (const float*)d_in[1];
    const int*   idx32  = (const int*)d_in[2];
    const float* gumbel = (const float*)d_in[3];
    const float* W      = (const float*)d_in[4];
    float* out = (float*)d_out;

    cudaFuncSetAttribute(gemm_kernel,
                         cudaFuncAttributeMaxDynamicSharedMemorySize, SMEM_DYN);

    init_kernel<<<1, 32>>>();
    select_kernel<<<(B_N + 255) / 256, 256>>>(envs, idx32, gumbel);
    build_tiles_kernel<<<1, 32>>>();
    penalty_kernel<<<PEN_GRID, PEN_BLK>>>(W, hidden);

    gemm_kernel<<<GRID_GEMM, 128, SMEM_DYN>>>(out);

    if (out_size > B_N * L_N)
        finalize_kernel<<<1, 32>>>(out + (size_t)B_N * L_N);
}

// round 13
// speedup vs baseline: 2.0687x; 2.0687x over previous
#include <cuda_runtime.h>
#include <cuda_fp16.h>
#include <cstdint>

#define B_N 2048
#define H_N 4096
#define E_N 8
#define L_N 512

// ---------------- scratch ----------------
__device__ int   g_counts[E_N];
__device__ int   g_rows[E_N][B_N];
__device__ float g_pen[25];
__device__ int   g_ntiles;
__device__ int   g_tile_ctr;
__device__ uint32_t g_tiles[512];

__device__ __align__(256) __half g_hid_h[B_N * H_N];
__device__ __align__(256) __half g_W_h[E_N * L_N * H_N];

__global__ void init_kernel() {
    int t = threadIdx.x;
    if (t < E_N) g_counts[t] = 0;
    if (t < 25)  g_pen[t]    = 0.0f;
    if (t == 0)  g_tile_ctr  = 0;
}

// ---------------- expert selection ----------------
__global__ void select_kernel(const float* __restrict__ envs,
                              const int* __restrict__ idx32,
                              const float* __restrict__ gumbel) {
    int b = blockIdx.x * blockDim.x + threadIdx.x;
    if (b >= B_N) return;
    int stride = (idx32[1] == 0) ? 2 : 1;   // int64-on-disk detection (idx = arange)
    int r = idx32[(size_t)b * stride];
    if (r < 0) r = 0;
    if (r >= B_N) r = B_N - 1;
    const float* ev = envs   + (size_t)r * E_N;
    const float* gv = gumbel + (size_t)b * E_N;
    float best = ev[0] + gv[0];
    int be = 0;
#pragma unroll
    for (int e = 1; e < E_N; e++) {
        float v = ev[e] + gv[e];
        if (v > best) { best = v; be = e; }
    }
    int pos = atomicAdd(&g_counts[be], 1);
    g_rows[be][pos] = b;
}

// ---------------- balanced tile list ----------------
// tile = (expert, 64-row m-chunk, 128-col l-block); enc = e<<12 | m<<4 | l
__global__ void build_tiles_kernel() {
    if (threadIdx.x == 0) {
        int n = 0;
        for (int e = 0; e < E_N; e++) {
            int mc = (g_counts[e] + 63) >> 6;
            for (int m = 0; m < mc; m++)
                for (int l = 0; l < 4; l++)
                    g_tiles[n++] = (e << 12) | (m << 4) | l;
        }
        g_ntiles = n;
    }
}

// ---------------- hidden -> fp16 ----------------
__global__ void __launch_bounds__(256)
convert_hidden_kernel(const float* __restrict__ hidden) {
    const int n4 = B_N * H_N / 4;
    const float4* hv = (const float4*)hidden;
    uint2* hh = (uint2*)g_hid_h;
    int stride = gridDim.x * blockDim.x;
    for (int i = blockIdx.x * blockDim.x + threadIdx.x; i < n4; i += stride) {
        float4 v = hv[i];
        __half2 h01 = __floats2half2_rn(v.x, v.y);
        __half2 h23 = __floats2half2_rn(v.z, v.w);
        uint2 p;
        p.x = *reinterpret_cast<uint32_t*>(&h01);
        p.y = *reinterpret_cast<uint32_t*>(&h23);
        hh[i] = p;
    }
}

// ------- penalty + W -> fp16, double-buffered single pass -------
#define PEN_GRID 1024
#define PEN_BLK  128

__global__ void __launch_bounds__(PEN_BLK, 4)
penalty_kernel(const float* __restrict__ W) {
    const int LH4 = (L_N * H_N) / 4;
    const float4* Wv = (const float4*)W;
    uint2* wh = (uint2*)g_W_h;
    const int stride = PEN_GRID * PEN_BLK;
    const int iters = LH4 / stride;   // 4

    float q[8], c[8], l1[8], ss = 0.0f;
#pragma unroll
    for (int e = 0; e < 8; e++) { q[e] = 0.f; c[e] = 0.f; l1[e] = 0.f; }

    int i = blockIdx.x * PEN_BLK + threadIdx.x;

    float4 buf[8];
#pragma unroll
    for (int e = 0; e < 8; e++) buf[e] = Wv[(size_t)e * LH4 + i];

    for (int it = 0; it < iters; it++) {
        float4 nxt[8];
        int i2 = i + stride;
        if (it + 1 < iters) {
#pragma unroll
            for (int e = 0; e < 8; e++) nxt[e] = Wv[(size_t)e * LH4 + i2];
        }
#pragma unroll
        for (int e = 0; e < 8; e++) {
            float4 v = buf[e];
            __half2 h01 = __floats2half2_rn(v.x, v.y);
            __half2 h23 = __floats2half2_rn(v.z, v.w);
            uint2 p;
            p.x = *reinterpret_cast<uint32_t*>(&h01);
            p.y = *reinterpret_cast<uint32_t*>(&h23);
            wh[(size_t)e * LH4 + i] = p;
        }
#pragma unroll
        for (int comp = 0; comp < 4; comp++) {
            float we[8];
#pragma unroll
            for (int e = 0; e < 8; e++) {
                float4 t = buf[e];
                we[e] = (comp == 0) ? t.x : (comp == 1) ? t.y : (comp == 2) ? t.z : t.w;
            }
            float s = 0.f;
#pragma unroll
            for (int e = 0; e < 8; e++) s += we[e];
            ss = fmaf(s, s, ss);
#pragma unroll
            for (int e = 0; e < 8; e++) {
                q[e]  = fmaf(we[e], we[e], q[e]);
                c[e]  = fmaf(we[e], s,     c[e]);
                l1[e] += fabsf(we[e]);
            }
        }
        if (it + 1 < iters) {
#pragma unroll
            for (int e = 0; e < 8; e++) buf[e] = nxt[e];
            i = i2;
        }
    }

    __shared__ float red[25][136];
    int tid = threadIdx.x;
#pragma unroll
    for (int e = 0; e < 8; e++) {
        red[e][tid]      = q[e];
        red[8 + e][tid]  = c[e];
        red[16 + e][tid] = l1[e];
    }
    red[24][tid] = ss;
    __syncthreads();
    if (tid < 25) {
        float s = 0.f;
#pragma unroll 8
        for (int j = 0; j < PEN_BLK; j++) s += red[tid][j];
        atomicAdd(&g_pen[tid], s);
    }
}

__global__ void finalize_kernel(float* __restrict__ pen_out) {
    if (threadIdx.x == 0) {
        float acc = 0.f;
        float ss = g_pen[24];
#pragma unroll
        for (int e = 0; e < 8; e++) {
            float diff = g_pen[e] - 0.25f * g_pen[8 + e] + ss * (1.0f / 64.0f);
            float l1 = g_pen[16 + e];
            acc += diff / (l1 * l1);
        }
        pen_out[0] = acc * 0.125f;
    }
}

// ====== persistent fp16 tensor-core grouped GEMM (1 CTA/SM, TK=128) ======
// CTA tile 64(M) x 128(N) x 128(K); 256 threads = 8 warps (2M x 4N), warp 32x32.
// K=128 stored as two stacked 64-half blocks; per-block layout identical to R11.
// Stage (bytes): A[2]x8K | B[2]x16K = 48KB; 3 stages = 144KB.
// Swizzle: row stride 64 halves (128B), 16B chunk phys = chunk ^ (row & 7).

#define TMB 64
#define TNB 128
#define TK 128
#define NSTAGE 3
#define STG_B 49152
#define NIT (H_N / TK)          // 32
#define SMEM_DYN (NSTAGE * STG_B + 1024)
#define GRID_GEMM 148

static __device__ __forceinline__ uint32_t s2u(const void* p) {
    return (uint32_t)__cvta_generic_to_shared(p);
}
static __device__ __forceinline__ void cp16(uint32_t s, const __half* g, bool pred) {
    int sz = pred ? 16 : 0;
    asm volatile("cp.async.cg.shared.global [%0], [%1], 16, %2;"
                 :: "r"(s), "l"(g), "r"(sz));
}

#define LDSM4(r0, r1, r2, r3, a) \
    asm volatile("ldmatrix.sync.aligned.m8n8.x4.shared.b16 {%0,%1,%2,%3}, [%4];" \
                 : "=r"(r0), "=r"(r1), "=r"(r2), "=r"(r3) : "r"(a))

#define MMAF16(d, A, b0, b1) \
    asm volatile("mma.sync.aligned.m16n8k16.row.col.f32.f16.f16.f32 " \
                 "{%0,%1,%2,%3}, {%4,%5,%6,%7}, {%8,%9}, {%0,%1,%2,%3};" \
                 : "+f"((d)[0]), "+f"((d)[1]), "+f"((d)[2]), "+f"((d)[3]) \
                 : "r"((A)[0]), "r"((A)[1]), "r"((A)[2]), "r"((A)[3]), \
                   "r"(b0), "r"(b1))

extern __shared__ char dyn_raw[];

__global__ void __launch_bounds__(256, 1)
gemm_kernel(float* __restrict__ out) {
    __shared__ int rowids[TMB];
    __shared__ int s_tile;

    int tid = threadIdx.x;
    int wid = tid >> 5, lane = tid & 31;

    uint32_t sbase = (s2u(dyn_raw) + 1023) & ~1023u;
    uint32_t stb[NSTAGE];
#pragma unroll
    for (int s = 0; s < NSTAGE; s++) stb[s] = sbase + s * STG_B;

    // loader geometry per 64-k block: A 512 slots (2/thr), B 1024 slots (4/thr)
    int lrow = tid >> 3;              // 0..31
    int lcc  = tid & 7;
    int lphys = lcc ^ (lrow & 7);     // row&7 invariant (rows step by 32)
    int sOffA[2], sOffB[4];
#pragma unroll
    for (int i = 0; i < 2; i++) sOffA[i] = ((lrow + i * 32) * 64 + lphys * 8) * 2;
#pragma unroll
    for (int i = 0; i < 4; i++) sOffB[i] = ((lrow + i * 32) * 64 + lphys * 8) * 2;

    // warp geometry (32x32 warp tile): 2 warps on M, 4 on N
    int wm = (wid & 1) * 32;
    int wn = (wid >> 1) * 32;
    int a_r = lane & 15, a_h = lane >> 4;
    int b_g = lane >> 3, b_sub = b_g >> 1, b_h = b_g & 1, b_r = lane & 7;

    int arow[2], axr[2];
#pragma unroll
    for (int mt = 0; mt < 2; mt++) {
        int r = wm + mt * 16 + a_r;
        arow[mt] = r * 64; axr[mt] = r & 7;
    }
    int brow[2], bxr[2];
#pragma unroll
    for (int p = 0; p < 2; p++) {
        int r = wn + p * 16 + b_sub * 8 + b_r;
        brow[p] = r * 64; bxr[p] = r & 7;
    }
    int gid = lane >> 2, tig = lane & 3;

    for (;;) {
        __syncthreads();   // previous tile fully done
        if (tid == 0) s_tile = atomicAdd(&g_tile_ctr, 1);
        __syncthreads();
        int t = s_tile;
        if (t >= g_ntiles) break;

        uint32_t enc = g_tiles[t];
        int e = enc >> 12;
        int mch = (enc >> 4) & 255;
        int l_base = (enc & 15) * TNB;
        int cnt = g_counts[e];

        if (tid < TMB) {
            int i = mch * TMB + tid;
            rowids[tid] = (i < cnt) ? g_rows[e][i] : -1;
        }
        __syncthreads();

        const __half* gA[2];
        const __half* gB[4];
        bool apred[2];
#pragma unroll
        for (int i = 0; i < 2; i++) {
            int row = lrow + i * 32;
            int g = rowids[row];
            apred[i] = (g >= 0);
            gA[i] = g_hid_h + (size_t)(apred[i] ? g : 0) * H_N + lcc * 8;
        }
#pragma unroll
        for (int i = 0; i < 4; i++) {
            int row = lrow + i * 32;
            gB[i] = g_W_h + ((size_t)e * L_N + l_base + row) * H_N + lcc * 8;
        }

        float acc[2][4][4];
#pragma unroll
        for (int mt = 0; mt < 2; mt++)
#pragma unroll
            for (int nt = 0; nt < 4; nt++)
#pragma unroll
                for (int j = 0; j < 4; j++) acc[mt][nt][j] = 0.f;

        // preload stages 0,1 (each stage = 2 k-blocks of 64)
#pragma unroll
        for (int p = 0; p < NSTAGE - 1; p++) {
            uint32_t b = stb[p];
            int koff = p * TK;
#pragma unroll
            for (int kb = 0; kb < 2; kb++) {
                int ko = koff + kb * 64;
#pragma unroll
                for (int i = 0; i < 2; i++)
                    cp16(b + kb * 8192 + sOffA[i], gA[i] + ko, apred[i]);
#pragma unroll
                for (int i = 0; i < 4; i++)
                    cp16(b + 16384 + kb * 16384 + sOffB[i], gB[i] + ko, true);
            }
            asm volatile("cp.async.commit_group;");
        }

        int cur = 0, nxt = NSTAGE - 1;
        for (int it = 0; it < NIT; it++) {
            asm volatile("cp.async.wait_group 1;");
            __syncthreads();

            int nc = it + NSTAGE - 1;
            if (nc < NIT) {
                uint32_t b = stb[nxt];
                int koff = nc * TK;
#pragma unroll
                for (int kb = 0; kb < 2; kb++) {
                    int ko = koff + kb * 64;
#pragma unroll
                    for (int i = 0; i < 2; i++)
                        cp16(b + kb * 8192 + sOffA[i], gA[i] + ko, apred[i]);
#pragma unroll
                    for (int i = 0; i < 4; i++)
                        cp16(b + 16384 + kb * 16384 + sOffB[i], gB[i] + ko, true);
                }
            }
            asm volatile("cp.async.commit_group;");

#pragma unroll
            for (int s4 = 0; s4 < 8; s4++) {         // 8 k16 steps over TK=128
                uint32_t AS = stb[cur] + (s4 >> 2) * 8192;
                uint32_t BS = stb[cur] + 16384 + (s4 >> 2) * 16384;
                int s4l = s4 & 3;
                uint32_t af[2][4], bf[4][2];
#pragma unroll
                for (int mt = 0; mt < 2; mt++) {
                    int ch = (2 * s4l + a_h) ^ axr[mt];
                    LDSM4(af[mt][0], af[mt][1], af[mt][2], af[mt][3],
                          AS + (arow[mt] + ch * 8) * 2);
                }
#pragma unroll
                for (int p = 0; p < 2; p++) {
                    int ch = (2 * s4l + b_h) ^ bxr[p];
                    uint32_t r0, r1, r2, r3;
                    LDSM4(r0, r1, r2, r3, BS + (brow[p] + ch * 8) * 2);
                    bf[2 * p][0] = r0; bf[2 * p][1] = r1;
                    bf[2 * p + 1][0] = r2; bf[2 * p + 1][1] = r3;
                }
                // 8 independent MMAs (each acc touched once per s4)
#pragma unroll
                for (int mt = 0; mt < 2; mt++)
#pragma unroll
                    for (int nt = 0; nt < 4; nt++)
                        MMAF16(acc[mt][nt], af[mt], bf[nt][0], bf[nt][1]);
            }
            cur = (cur + 1 == NSTAGE) ? 0 : cur + 1;
            nxt = (nxt + 1 == NSTAGE) ? 0 : nxt + 1;
        }

        // ---- epilogue ----
#pragma unroll
        for (int mt = 0; mt < 2; mt++) {
            int r0 = wm + mt * 16 + gid;
            int r1 = r0 + 8;
            int g0 = rowids[r0];
            int g1 = rowids[r1];
#pragma unroll
            for (int nt = 0; nt < 4; nt++) {
                int col = l_base + wn + nt * 8 + tig * 2;
                if (g0 >= 0)
                    *(float2*)(out + (size_t)g0 * L_N + col) =
                        make_float2(acc[mt][nt][0], acc[mt][nt][1]);
                if (g1 >= 0)
                    *(float2*)(out + (size_t)g1 * L_N + col) =
                        make_float2(acc[mt][nt][2], acc[mt][nt][3]);
            }
        }
    }
}

// ---------------- launch ----------------
extern "C" void kernel_launch(void* const* d_in, const int* in_sizes, int n_in,
                              void* d_out, int out_size) {
    const float* hidden = (const float*)d_in[0];
    const float* envs   = (const float*)d_in[1];
    const int*   idx32  = (const int*)d_in[2];
    const float* gumbel = (const float*)d_in[3];
    const float* W      = (const float*)d_in[4];
    float* out = (float*)d_out;

    cudaFuncSetAttribute(gemm_kernel,
                         cudaFuncAttributeMaxDynamicSharedMemorySize, SMEM_DYN);

    init_kernel<<<1, 32>>>();
    select_kernel<<<(B_N + 255) / 256, 256>>>(envs, idx32, gumbel);
    build_tiles_kernel<<<1, 32>>>();
    convert_hidden_kernel<<<1024, 256>>>(hidden);
    penalty_kernel<<<PEN_GRID, PEN_BLK>>>(W);

    gemm_kernel<<<GRID_GEMM, 256, SMEM_DYN>>>(out);

    if (out_size > B_N * L_N)
        finalize_kernel<<<1, 32>>>(out + (size_t)B_N * L_N);
}

// round 14
// speedup vs baseline: 2.0858x; 1.0082x over previous
#include <cuda_runtime.h>
#include <cuda_fp16.h>
#include <cstdint>

#define B_N 2048
#define H_N 4096
#define E_N 8
#define L_N 512

// ---------------- scratch ----------------
__device__ int   g_counts[E_N];
__device__ int   g_rows[E_N][B_N];
__device__ float g_pen[25];
__device__ int   g_ntiles;
__device__ int   g_tile_ctr;
__device__ uint32_t g_tiles[512];

__device__ __align__(256) __half g_hid_h[B_N * H_N];
__device__ __align__(256) __half g_W_h[E_N * L_N * H_N];

__global__ void init_kernel() {
    int t = threadIdx.x;
    if (t < E_N) g_counts[t] = 0;
    if (t < 25)  g_pen[t]    = 0.0f;
    if (t == 0)  g_tile_ctr  = 0;
}

// ---------------- expert selection ----------------
__global__ void select_kernel(const float* __restrict__ envs,
                              const int* __restrict__ idx32,
                              const float* __restrict__ gumbel) {
    int b = blockIdx.x * blockDim.x + threadIdx.x;
    if (b >= B_N) return;
    int stride = (idx32[1] == 0) ? 2 : 1;   // int64-on-disk detection (idx = arange)
    int r = idx32[(size_t)b * stride];
    if (r < 0) r = 0;
    if (r >= B_N) r = B_N - 1;
    const float* ev = envs   + (size_t)r * E_N;
    const float* gv = gumbel + (size_t)b * E_N;
    float best = ev[0] + gv[0];
    int be = 0;
#pragma unroll
    for (int e = 1; e < E_N; e++) {
        float v = ev[e] + gv[e];
        if (v > best) { best = v; be = e; }
    }
    int pos = atomicAdd(&g_counts[be], 1);
    g_rows[be][pos] = b;
}

// ---------------- balanced tile list ----------------
// tile = (expert, 64-row m-chunk, 128-col l-block); enc = e<<12 | m<<4 | l
__global__ void build_tiles_kernel() {
    if (threadIdx.x == 0) {
        int n = 0;
        for (int e = 0; e < E_N; e++) {
            int mc = (g_counts[e] + 63) >> 6;
            for (int m = 0; m < mc; m++)
                for (int l = 0; l < 4; l++)
                    g_tiles[n++] = (e << 12) | (m << 4) | l;
        }
        g_ntiles = n;
    }
}

// ---------------- hidden -> fp16 ----------------
__global__ void __launch_bounds__(256)
convert_hidden_kernel(const float* __restrict__ hidden) {
    const int n4 = B_N * H_N / 4;
    const float4* hv = (const float4*)hidden;
    uint2* hh = (uint2*)g_hid_h;
    int stride = gridDim.x * blockDim.x;
    for (int i = blockIdx.x * blockDim.x + threadIdx.x; i < n4; i += stride) {
        float4 v = hv[i];
        __half2 h01 = __floats2half2_rn(v.x, v.y);
        __half2 h23 = __floats2half2_rn(v.z, v.w);
        uint2 p;
        p.x = *reinterpret_cast<uint32_t*>(&h01);
        p.y = *reinterpret_cast<uint32_t*>(&h23);
        hh[i] = p;
    }
}

// ------- penalty + W -> fp16, double-buffered single pass -------
#define PEN_GRID 1024
#define PEN_BLK  128

__global__ void __launch_bounds__(PEN_BLK, 4)
penalty_kernel(const float* __restrict__ W) {
    const int LH4 = (L_N * H_N) / 4;
    const float4* Wv = (const float4*)W;
    uint2* wh = (uint2*)g_W_h;
    const int stride = PEN_GRID * PEN_BLK;
    const int iters = LH4 / stride;   // 4

    float q[8], c[8], l1[8], ss = 0.0f;
#pragma unroll
    for (int e = 0; e < 8; e++) { q[e] = 0.f; c[e] = 0.f; l1[e] = 0.f; }

    int i = blockIdx.x * PEN_BLK + threadIdx.x;

    float4 buf[8];
#pragma unroll
    for (int e = 0; e < 8; e++) buf[e] = Wv[(size_t)e * LH4 + i];

    for (int it = 0; it < iters; it++) {
        float4 nxt[8];
        int i2 = i + stride;
        if (it + 1 < iters) {
#pragma unroll
            for (int e = 0; e < 8; e++) nxt[e] = Wv[(size_t)e * LH4 + i2];
        }
#pragma unroll
        for (int e = 0; e < 8; e++) {
            float4 v = buf[e];
            __half2 h01 = __floats2half2_rn(v.x, v.y);
            __half2 h23 = __floats2half2_rn(v.z, v.w);
            uint2 p;
            p.x = *reinterpret_cast<uint32_t*>(&h01);
            p.y = *reinterpret_cast<uint32_t*>(&h23);
            wh[(size_t)e * LH4 + i] = p;
        }
#pragma unroll
        for (int comp = 0; comp < 4; comp++) {
            float we[8];
#pragma unroll
            for (int e = 0; e < 8; e++) {
                float4 t = buf[e];
                we[e] = (comp == 0) ? t.x : (comp == 1) ? t.y : (comp == 2) ? t.z : t.w;
            }
            float s = 0.f;
#pragma unroll
            for (int e = 0; e < 8; e++) s += we[e];
            ss = fmaf(s, s, ss);
#pragma unroll
            for (int e = 0; e < 8; e++) {
                q[e]  = fmaf(we[e], we[e], q[e]);
                c[e]  = fmaf(we[e], s,     c[e]);
                l1[e] += fabsf(we[e]);
            }
        }
        if (it + 1 < iters) {
#pragma unroll
            for (int e = 0; e < 8; e++) buf[e] = nxt[e];
            i = i2;
        }
    }

    __shared__ float red[25][136];
    int tid = threadIdx.x;
#pragma unroll
    for (int e = 0; e < 8; e++) {
        red[e][tid]      = q[e];
        red[8 + e][tid]  = c[e];
        red[16 + e][tid] = l1[e];
    }
    red[24][tid] = ss;
    __syncthreads();
    if (tid < 25) {
        float s = 0.f;
#pragma unroll 8
        for (int j = 0; j < PEN_BLK; j++) s += red[tid][j];
        atomicAdd(&g_pen[tid], s);
    }
}

__global__ void finalize_kernel(float* __restrict__ pen_out) {
    if (threadIdx.x == 0) {
        float acc = 0.f;
        float ss = g_pen[24];
#pragma unroll
        for (int e = 0; e < 8; e++) {
            float diff = g_pen[e] - 0.25f * g_pen[8 + e] + ss * (1.0f / 64.0f);
            float l1 = g_pen[16 + e];
            acc += diff / (l1 * l1);
        }
        pen_out[0] = acc * 0.125f;
    }
}

// ====== persistent fp16 tensor-core grouped GEMM (1 CTA/SM, TK=128) ======
// CTA tile 64(M) x 128(N) x 128(K); 256 threads = 8 warps (2M x 4N), warp 32x32.
// K=128 stored as two stacked 64-half blocks.
// Stage (bytes): A[2]x8K | B[2]x16K = 48KB; 3 stages = 144KB.
// Register fragment double-buffering: ldsm for s4+1 issued before s4's MMAs retire.
// Swizzle: row stride 64 halves (128B), 16B chunk phys = chunk ^ (row & 7).

#define TMB 64
#define TNB 128
#define TK 128
#define NSTAGE 3
#define STG_B 49152
#define NIT (H_N / TK)          // 32
#define SMEM_DYN (NSTAGE * STG_B + 1024)
#define GRID_GEMM 148

static __device__ __forceinline__ uint32_t s2u(const void* p) {
    return (uint32_t)__cvta_generic_to_shared(p);
}
static __device__ __forceinline__ void cp16(uint32_t s, const __half* g, bool pred) {
    int sz = pred ? 16 : 0;
    asm volatile("cp.async.cg.shared.global [%0], [%1], 16, %2;"
                 :: "r"(s), "l"(g), "r"(sz));
}

#define LDSM4(r0, r1, r2, r3, a) \
    asm volatile("ldmatrix.sync.aligned.m8n8.x4.shared.b16 {%0,%1,%2,%3}, [%4];" \
                 : "=r"(r0), "=r"(r1), "=r"(r2), "=r"(r3) : "r"(a))

#define MMAF16(d, A, b0, b1) \
    asm volatile("mma.sync.aligned.m16n8k16.row.col.f32.f16.f16.f32 " \
                 "{%0,%1,%2,%3}, {%4,%5,%6,%7}, {%8,%9}, {%0,%1,%2,%3};" \
                 : "+f"((d)[0]), "+f"((d)[1]), "+f"((d)[2]), "+f"((d)[3]) \
                 : "r"((A)[0]), "r"((A)[1]), "r"((A)[2]), "r"((A)[3]), \
                   "r"(b0), "r"(b1))

// Load one k16-step's fragments (A: 2 LDSM4, B: 2 LDSM4) into buffer BUF.
#define LOAD_FRAG(BUF, S4) do {                                              \
    uint32_t _AS = base + ((S4) >> 2) * 8192;                                \
    uint32_t _BS = base + 16384 + ((S4) >> 2) * 16384;                       \
    int _s4l = (S4) & 3;                                                     \
    _Pragma("unroll")                                                        \
    for (int _mt = 0; _mt < 2; _mt++) {                                      \
        int _ch = (2 * _s4l + a_h) ^ axr[_mt];                               \
        LDSM4(af[BUF][_mt][0], af[BUF][_mt][1], af[BUF][_mt][2],             \
              af[BUF][_mt][3], _AS + (arow[_mt] + _ch * 8) * 2);             \
    }                                                                        \
    _Pragma("unroll")                                                        \
    for (int _p = 0; _p < 2; _p++) {                                         \
        int _ch = (2 * _s4l + b_h) ^ bxr[_p];                                \
        uint32_t _r0, _r1, _r2, _r3;                                         \
        LDSM4(_r0, _r1, _r2, _r3, _BS + (brow[_p] + _ch * 8) * 2);           \
        bf[BUF][2 * _p][0] = _r0;     bf[BUF][2 * _p][1] = _r1;              \
        bf[BUF][2 * _p + 1][0] = _r2; bf[BUF][2 * _p + 1][1] = _r3;          \
    }                                                                        \
} while (0)

extern __shared__ char dyn_raw[];

__global__ void __launch_bounds__(256, 1)
gemm_kernel(float* __restrict__ out) {
    __shared__ int rowids[TMB];
    __shared__ int s_tile;

    int tid = threadIdx.x;
    int wid = tid >> 5, lane = tid & 31;

    uint32_t sbase = (s2u(dyn_raw) + 1023) & ~1023u;
    uint32_t stb[NSTAGE];
#pragma unroll
    for (int s = 0; s < NSTAGE; s++) stb[s] = sbase + s * STG_B;

    // loader geometry per 64-k block: A 512 slots (2/thr), B 1024 slots (4/thr)
    int lrow = tid >> 3;              // 0..31
    int lcc  = tid & 7;
    int lphys = lcc ^ (lrow & 7);     // row&7 invariant (rows step by 32)
    int sOffA[2], sOffB[4];
#pragma unroll
    for (int i = 0; i < 2; i++) sOffA[i] = ((lrow + i * 32) * 64 + lphys * 8) * 2;
#pragma unroll
    for (int i = 0; i < 4; i++) sOffB[i] = ((lrow + i * 32) * 64 + lphys * 8) * 2;

    // warp geometry (32x32 warp tile): 2 warps on M, 4 on N
    int wm = (wid & 1) * 32;
    int wn = (wid >> 1) * 32;
    int a_r = lane & 15, a_h = lane >> 4;
    int b_g = lane >> 3, b_sub = b_g >> 1, b_h = b_g & 1, b_r = lane & 7;

    int arow[2], axr[2];
#pragma unroll
    for (int mt = 0; mt < 2; mt++) {
        int r = wm + mt * 16 + a_r;
        arow[mt] = r * 64; axr[mt] = r & 7;
    }
    int brow[2], bxr[2];
#pragma unroll
    for (int p = 0; p < 2; p++) {
        int r = wn + p * 16 + b_sub * 8 + b_r;
        brow[p] = r * 64; bxr[p] = r & 7;
    }
    int gid = lane >> 2, tig = lane & 3;

    for (;;) {
        __syncthreads();   // previous tile fully done
        if (tid == 0) s_tile = atomicAdd(&g_tile_ctr, 1);
        __syncthreads();
        int t = s_tile;
        if (t >= g_ntiles) break;

        uint32_t enc = g_tiles[t];
        int e = enc >> 12;
        int mch = (enc >> 4) & 255;
        int l_base = (enc & 15) * TNB;
        int cnt = g_counts[e];

        if (tid < TMB) {
            int i = mch * TMB + tid;
            rowids[tid] = (i < cnt) ? g_rows[e][i] : -1;
        }
        __syncthreads();

        const __half* gA[2];
        const __half* gB[4];
        bool apred[2];
#pragma unroll
        for (int i = 0; i < 2; i++) {
            int row = lrow + i * 32;
            int g = rowids[row];
            apred[i] = (g >= 0);
            gA[i] = g_hid_h + (size_t)(apred[i] ? g : 0) * H_N + lcc * 8;
        }
#pragma unroll
        for (int i = 0; i < 4; i++) {
            int row = lrow + i * 32;
            gB[i] = g_W_h + ((size_t)e * L_N + l_base + row) * H_N + lcc * 8;
        }

        float acc[2][4][4];
#pragma unroll
        for (int mt = 0; mt < 2; mt++)
#pragma unroll
            for (int nt = 0; nt < 4; nt++)
#pragma unroll
                for (int j = 0; j < 4; j++) acc[mt][nt][j] = 0.f;

        // preload stages 0,1 (each stage = 2 k-blocks of 64)
#pragma unroll
        for (int p = 0; p < NSTAGE - 1; p++) {
            uint32_t b = stb[p];
            int koff = p * TK;
#pragma unroll
            for (int kb = 0; kb < 2; kb++) {
                int ko = koff + kb * 64;
#pragma unroll
                for (int i = 0; i < 2; i++)
                    cp16(b + kb * 8192 + sOffA[i], gA[i] + ko, apred[i]);
#pragma unroll
                for (int i = 0; i < 4; i++)
                    cp16(b + 16384 + kb * 16384 + sOffB[i], gB[i] + ko, true);
            }
            asm volatile("cp.async.commit_group;");
        }

        int cur = 0, nxt = NSTAGE - 1;
        for (int it = 0; it < NIT; it++) {
            asm volatile("cp.async.wait_group 1;");
            __syncthreads();

            int nc = it + NSTAGE - 1;
            if (nc < NIT) {
                uint32_t b = stb[nxt];
                int koff = nc * TK;
#pragma unroll
                for (int kb = 0; kb < 2; kb++) {
                    int ko = koff + kb * 64;
#pragma unroll
                    for (int i = 0; i < 2; i++)
                        cp16(b + kb * 8192 + sOffA[i], gA[i] + ko, apred[i]);
#pragma unroll
                    for (int i = 0; i < 4; i++)
                        cp16(b + 16384 + kb * 16384 + sOffB[i], gB[i] + ko, true);
                }
            }
            asm volatile("cp.async.commit_group;");

            uint32_t base = stb[cur];
            uint32_t af[2][2][4], bf[2][4][2];

            LOAD_FRAG(0, 0);
#pragma unroll
            for (int s4 = 0; s4 < 8; s4++) {
                int cb = s4 & 1, nb = cb ^ 1;
                if (s4 < 7) LOAD_FRAG(nb, s4 + 1);
                // 8 independent MMAs on current buffer (overlap ldsm above)
#pragma unroll
                for (int mt = 0; mt < 2; mt++)
#pragma unroll
                    for (int nt = 0; nt < 4; nt++)
                        MMAF16(acc[mt][nt], af[cb][mt], bf[cb][nt][0], bf[cb][nt][1]);
            }
            cur = (cur + 1 == NSTAGE) ? 0 : cur + 1;
            nxt = (nxt + 1 == NSTAGE) ? 0 : nxt + 1;
        }

        // ---- epilogue ----
#pragma unroll
        for (int mt = 0; mt < 2; mt++) {
            int r0 = wm + mt * 16 + gid;
            int r1 = r0 + 8;
            int g0 = rowids[r0];
            int g1 = rowids[r1];
#pragma unroll
            for (int nt = 0; nt < 4; nt++) {
                int col = l_base + wn + nt * 8 + tig * 2;
                if (g0 >= 0)
                    *(float2*)(out + (size_t)g0 * L_N + col) =
                        make_float2(acc[mt][nt][0], acc[mt][nt][1]);
                if (g1 >= 0)
                    *(float2*)(out + (size_t)g1 * L_N + col) =
                        make_float2(acc[mt][nt][2], acc[mt][nt][3]);
            }
        }
    }
}

// ---------------- launch ----------------
extern "C" void kernel_launch(void* const* d_in, const int* in_sizes, int n_in,
                              void* d_out, int out_size) {
    const float* hidden = (const float*)d_in[0];
    const float* envs   = (const float*)d_in[1];
    const int*   idx32  = (const int*)d_in[2];
    const float* gumbel = (const float*)d_in[3];
    const float* W      = (const float*)d_in[4];
    float* out = (float*)d_out;

    cudaFuncSetAttribute(gemm_kernel,
                         cudaFuncAttributeMaxDynamicSharedMemorySize, SMEM_DYN);

    init_kernel<<<1, 32>>>();
    select_kernel<<<(B_N + 255) / 256, 256>>>(envs, idx32, gumbel);
    build_tiles_kernel<<<1, 32>>>();
    convert_hidden_kernel<<<1024, 256>>>(hidden);
    penalty_kernel<<<PEN_GRID, PEN_BLK>>>(W);

    gemm_kernel<<<GRID_GEMM, 256, SMEM_DYN>>>(out);

    if (out_size > B_N * L_N)
        finalize_kernel<<<1, 32>>>(out + (size_t)B_N * L_N);
}